// round 17
// baseline (speedup 1.0000x reference)
#include <cuda_runtime.h>
#include <cuda_fp16.h>
#include <cstdint>

// Problem constants
#define B_   16
#define C_   256
#define HW_  1024
#define K_   8192
#define N_   16384            // tokens
#define NQE  4194304          // qe elems

// Tiling
#define TM 128                 // tokens per CTA
#define TN 128                 // codes per CTA
#define NCHUNK 8               // chunks of 32 floats (16 f16x2 words)
#define NCAND 256              // candidates per token
#define MARGIN 3.5f            // rerank margin: fp16-accum noise + key truncation
#define NSTAGE 3

// smem in uint2 units. A: [q 8][t 128] stride 132 (132 mod 16 = 4, conflict-free)
// B: [nr 128][q 8] stride 12 (g*12+tg distinct per phase)
#define ASTU2 132
#define A_U2 (8 * ASTU2)                // 1056
#define BSTU2 12
#define B_U2 (128 * BSTU2)              // 1536
#define STAGE_U2 (A_U2 + B_U2)          // 2592
#define STAGE_BYTES (STAGE_U2 * 8)      // 20736
#define SMEM_BYTES (NSTAGE * STAGE_BYTES)  // 62208

// Scratch
__device__ uint32_t g_cand[(size_t)N_ * NCAND];             // 16MB packed keys
__device__ uint2 g_xp2[(size_t)B_ * 64 * HW_];              // 8MB x, [b][chunk][q][t]
__device__ uint2 g_cbp2[(size_t)K_ * 64];                   // 4MB cb, [n][chunk][q]
__device__ float g_xt[(size_t)B_ * HW_ * C_];               // 16MB fp32 x, [b][hw][c]
__device__ unsigned int g_idx[N_];
__device__ float g_cnorm[K_];
__device__ float g_partial[N_ / 32];

__device__ __forceinline__ unsigned int fkey(float f) {
    unsigned int b = __float_as_uint(f);
    return (b & 0x80000000u) ? ~b : (b | 0x80000000u);
}
__device__ __forceinline__ float unfkey(unsigned int k) {
    unsigned int b = (k & 0x80000000u) ? (k & 0x7FFFFFFFu) : ~k;
    return __uint_as_float(b);
}
__device__ __forceinline__ uint32_t h_pair(float v0, float v1) {
    __half2 hp = __floats2half2_rn(v0, v1);
    return *(uint32_t*)&hp;
}
__device__ __forceinline__ uint32_t smem_u32(const void* p) {
    uint32_t a;
    asm("{ .reg .u64 t; cvta.to.shared.u64 t, %1; cvt.u32.u64 %0, t; }"
        : "=r"(a) : "l"(p));
    return a;
}
__device__ __forceinline__ void cp16(uint32_t dst, const void* src) {
    asm volatile("cp.async.cg.shared.global [%0], [%1], 16;"
                 :: "r"(dst), "l"(src));
}

#define MMA_F16ACC(D, A, B0, B1)                                            \
    asm volatile("mma.sync.aligned.m16n8k16.row.col.f16.f16.f16.f16 "       \
        "{%0,%1},{%2,%3,%4,%5},{%6,%7},{%0,%1};"                            \
        : "+r"((D)[0]), "+r"((D)[1])                                        \
        : "r"((A)[0]), "r"((A)[1]), "r"((A)[2]), "r"((A)[3]),               \
          "r"(B0), "r"(B1))

// ---------------------------------------------------------------------------
// Kernel 0a: preconvert x -> packed f16-pair uint2, layout [b][chunk][q][t].
// q in 0..7 maps to word pair (w, w+4), w = q<4 ? q : q+4.
__global__ void pconv_x_kernel(const float* __restrict__ x) {
    const int blk = blockIdx.x;              // (b*8 + k)*8 + q
    const int q = blk & 7;
    const int k = (blk >> 3) & 7;
    const int b = blk >> 6;
    const int w = (q < 4) ? q : q + 4;
    const int c1 = 2 * (k * 16 + w);         // channel of word kb; kb+4 -> c1+8
    const float4* r0 = (const float4*)(x + ((size_t)(b * C_ + c1)) * HW_);
    const float4* r1 = (const float4*)(x + ((size_t)(b * C_ + c1 + 1)) * HW_);
    const float4* r2 = (const float4*)(x + ((size_t)(b * C_ + c1 + 8)) * HW_);
    const float4* r3 = (const float4*)(x + ((size_t)(b * C_ + c1 + 9)) * HW_);
    const int t4 = threadIdx.x;              // 4 tokens per thread
    float4 v0 = r0[t4], v1 = r1[t4], v2 = r2[t4], v3 = r3[t4];
    uint4 o1, o2;
    o1.x = h_pair(v0.x, v1.x);  o1.y = h_pair(v2.x, v3.x);
    o1.z = h_pair(v0.y, v1.y);  o1.w = h_pair(v2.y, v3.y);
    o2.x = h_pair(v0.z, v1.z);  o2.y = h_pair(v2.z, v3.z);
    o2.z = h_pair(v0.w, v1.w);  o2.w = h_pair(v2.w, v3.w);
    uint4* orow = (uint4*)(g_xp2 + (size_t)blk * HW_);
    orow[2 * t4] = o1;
    orow[2 * t4 + 1] = o2;
}

// Kernel 0b: preconvert codebook -> packed uint2 [n][chunk][q], fused cnorm.
__global__ void pconv_cb_kernel(const float* __restrict__ cb) {
    int code = blockIdx.x * 8 + (threadIdx.x >> 5);
    int lane = threadIdx.x & 31;
    const float* row = cb + (size_t)code * C_;
    uint2* orow = g_cbp2 + (size_t)code * 64;
    float s = 0.0f;
#pragma unroll
    for (int rr = 0; rr < 2; rr++) {
        int idx = lane + 32 * rr;            // k*8 + q
        int k = idx >> 3, q = idx & 7;
        int w = (q < 4) ? q : q + 4;
        int c1 = 2 * (k * 16 + w);
        float2 a = *(const float2*)(row + c1);
        float2 bq = *(const float2*)(row + c1 + 8);
        s += a.x * a.x + a.y * a.y + bq.x * bq.x + bq.y * bq.y;
        uint2 o;
        o.x = h_pair(a.x, a.y);
        o.y = h_pair(bq.x, bq.y);
        orow[idx] = o;
    }
#pragma unroll
    for (int off = 16; off; off >>= 1)
        s += __shfl_xor_sync(0xFFFFFFFFu, s, off);
    if (lane == 0) g_cnorm[code] = s;
}

// Kernel 0c: transpose x -> fp32 [b][hw][c] (coalesced both sides).
__global__ void pconv_xt_kernel(const float* __restrict__ x) {
    __shared__ float sm[32][33];
    const int bx = blockIdx.x;
    const int b = bx >> 8;
    const int c0 = ((bx >> 5) & 7) * 32;
    const int hw0 = (bx & 31) * 32;
    const int tid = threadIdx.x;
    const int i = tid >> 5, j = tid & 31;
#pragma unroll
    for (int r = 0; r < 4; r++) {
        int row = i + 8 * r;
        sm[row][j] = x[((size_t)(b * C_ + c0 + row)) * HW_ + hw0 + j];
    }
    __syncthreads();
#pragma unroll
    for (int r = 0; r < 4; r++) {
        int row = i + 8 * r;
        g_xt[((size_t)(b * HW_ + hw0 + row)) * C_ + c0 + j] = sm[j][row];
    }
}

// ---------------------------------------------------------------------------
// Kernel 2: fp16 screening GEMM, packed LDS.64 fragments, 3-stage pipeline,
// one __syncthreads per chunk. grid=(128,64), block=256 (4m x 2n warps).
__global__ void __launch_bounds__(256, 3)
argmin_mma_kernel() {
    extern __shared__ uint2 smem2[];
    __shared__ float cnS[TN];

    const int tid = threadIdx.x;
    const int wid = tid >> 5;
    const int lane = tid & 31;
    const int g  = lane >> 2;
    const int tg = lane & 3;
    const int m0w = (wid & 3) * 32;
    const int n0w = (wid >> 2) * 64;

    const int n0tok = blockIdx.x * TM;
    const int b   = n0tok >> 10;
    const int hw0 = n0tok & 1023;
    const int j0  = blockIdx.y * TN;

    if (tid < TN) cnS[tid] = g_cnorm[j0 + tid];

    const uint32_t sbase = smem_u32(smem2);

    // hoisted fill addressing. A tile: 8 q-rows x 128 t (uint2) = 512 granules
    const int aq = tid >> 6, ac = tid & 63;              // granule gi=tid and tid+256
    const int aq2 = (tid + 256) >> 6, ac2 = (tid + 256) & 63;
    const uint32_t dstA0 = (uint32_t)((aq * ASTU2 + ac * 2) * 8);
    const uint32_t dstA1 = (uint32_t)((aq2 * ASTU2 + ac2 * 2) * 8);
    const uint2* srcA0 = g_xp2 + (size_t)b * (64 * HW_) + (size_t)aq * HW_
                       + hw0 + ac * 2;                    // +k*8*HW_
    const uint2* srcA1 = g_xp2 + (size_t)b * (64 * HW_) + (size_t)aq2 * HW_
                       + hw0 + ac2 * 2;
    // B tile: 128 rows x 8 q (uint2) = 512 granules
    const int bnr = tid >> 2, bq = (tid & 3) * 2;
    const int bnr2 = (tid + 256) >> 2, bq2 = ((tid + 256) & 3) * 2;
    const uint32_t dstB0 = (uint32_t)(A_U2 * 8 + (bnr * BSTU2 + bq) * 8);
    const uint32_t dstB1 = (uint32_t)(A_U2 * 8 + (bnr2 * BSTU2 + bq2) * 8);
    const uint2* srcB0 = g_cbp2 + (size_t)(j0 + bnr) * 64 + bq;    // +k*8
    const uint2* srcB1 = g_cbp2 + (size_t)(j0 + bnr2) * 64 + bq2;

    uint32_t d[2][8][2];
#pragma unroll
    for (int i = 0; i < 2; i++)
#pragma unroll
        for (int j = 0; j < 8; j++) {
            d[i][j][0] = 0u; d[i][j][1] = 0u;
        }

    auto fill = [&](int k, int stg) {
        uint32_t s0 = sbase + (uint32_t)(stg * STAGE_BYTES);
        size_t aoff = (size_t)k * (8 * HW_);
        int boff = k * 8;
        cp16(s0 + dstA0, srcA0 + aoff);
        cp16(s0 + dstA1, srcA1 + aoff);
        cp16(s0 + dstB0, srcB0 + boff);
        cp16(s0 + dstB1, srcB1 + boff);
        asm volatile("cp.async.commit_group;" ::: "memory");
    };

    auto mma_stage = [&](int stg) {
        const uint2* Au = smem2 + stg * STAGE_U2;
        const uint2* Bu = Au + A_U2;
#pragma unroll
        for (int kk = 0; kk < 2; kk++) {
            const int qb = kk * 4 + tg;
            uint32_t ah[2][4];
#pragma unroll
            for (int dm = 0; dm < 2; dm++) {
                int mc = m0w + 16 * dm + g;
                uint2 u0 = Au[qb * ASTU2 + mc];
                uint2 u1 = Au[qb * ASTU2 + mc + 8];
                ah[dm][0] = u0.x; ah[dm][1] = u1.x;
                ah[dm][2] = u0.y; ah[dm][3] = u1.y;
            }
#pragma unroll
            for (int dn = 0; dn < 8; dn++) {
                int nr = n0w + 8 * dn + g;
                uint2 bb = Bu[nr * BSTU2 + qb];
                MMA_F16ACC(d[0][dn], ah[0], bb.x, bb.y);
                MMA_F16ACC(d[1][dn], ah[1], bb.x, bb.y);
            }
        }
    };

    fill(0, 0);
    fill(1, 1);
#pragma unroll 1
    for (int k = 0; k < NCHUNK; k++) {
        asm volatile("cp.async.wait_group 1;" ::: "memory");
        __syncthreads();
        if (k + 2 < NCHUNK) fill(k + 2, (k + 2) % NSTAGE);
        else asm volatile("cp.async.commit_group;" ::: "memory");
        mma_stage(k % NSTAGE);
    }

    // epilogue: per n-warp top-2 per token row; packed 32-bit keys
#pragma unroll
    for (int dm = 0; dm < 2; dm++) {
#pragma unroll
        for (int h = 0; h < 2; h++) {
            uint32_t p1 = 0xFFFFFFFFu, p2 = 0xFFFFFFFFu;
#pragma unroll
            for (int dn = 0; dn < 8; dn++) {
                __half2 hp = *(__half2*)&d[dm][dn][h];
                float2 dv = __half22float2(hp);
#pragma unroll
                for (int e = 0; e < 2; e++) {
                    int col = n0w + 8 * dn + 2 * tg + e;
                    float sc = fmaf(-2.0f, e ? dv.y : dv.x, cnS[col]);
                    uint32_t p = (fkey(sc) & 0xFFFFE000u) |
                                 (uint32_t)(j0 + col);
                    if (p < p1) { p2 = p1; p1 = p; }
                    else if (p < p2) { p2 = p; }
                }
            }
#pragma unroll
            for (int off = 1; off <= 2; off <<= 1) {
                uint32_t q1 = __shfl_xor_sync(0xFFFFFFFFu, p1, off);
                uint32_t q2 = __shfl_xor_sync(0xFFFFFFFFu, p2, off);
                if (q1 < p1) { p2 = (p1 < q2) ? p1 : q2; p1 = q1; }
                else         { p2 = (p2 < q1) ? p2 : q1; }
            }
            if (tg == 0) {
                int tok = n0tok + m0w + 16 * dm + 8 * h + g;
                size_t base = (size_t)tok * NCAND + blockIdx.y * 4 + (wid >> 2) * 2;
                g_cand[base] = p1;
                g_cand[base + 1] = p2;
            }
        }
    }
}

// ---------------------------------------------------------------------------
// Kernel 3: exact fp32 rerank. One warp per token; coalesced x via g_xt.
__global__ void __launch_bounds__(256)
rerank_kernel(const float* __restrict__ cb) {
    const int wid = threadIdx.x >> 5;
    const int lane = threadIdx.x & 31;
    const int tok = blockIdx.x * 8 + wid;
    const uint32_t* cand = g_cand + (size_t)tok * NCAND;

    uint32_t v[8];
    uint32_t mn = 0xFFFFFFFFu;
#pragma unroll
    for (int r = 0; r < 8; r++) {
        v[r] = cand[lane + 32 * r];
        if (v[r] < mn) mn = v[r];
    }
#pragma unroll
    for (int off = 16; off; off >>= 1) {
        uint32_t o = __shfl_xor_sync(0xFFFFFFFFu, mn, off);
        if (o < mn) mn = o;
    }
    const float thr = unfkey(mn | 0x1FFFu) + MARGIN;

    const float* xt = g_xt + (size_t)tok * C_;
    float xr[8];
#pragma unroll
    for (int q = 0; q < 8; q++)
        xr[q] = xt[lane + 32 * q];

    float best_s = __uint_as_float(0x7F800000u);
    unsigned int best_j = 0xFFFFFFFFu;
#pragma unroll 1
    for (int r = 0; r < 8; r++) {
        float sf = unfkey(v[r] & 0xFFFFE000u);
        unsigned int m = __ballot_sync(0xFFFFFFFFu, sf <= thr);
        while (m) {
            int src = __ffs(m) - 1;
            m &= m - 1;
            uint32_t c = __shfl_sync(0xFFFFFFFFu, v[r], src);
            unsigned int j = c & 0x1FFFu;
            const float* row = cb + (size_t)j * C_;
            float dot = 0.0f;
#pragma unroll
            for (int q = 0; q < 8; q++)
                dot = fmaf(xr[q], row[lane + 32 * q], dot);
#pragma unroll
            for (int off = 16; off; off >>= 1)
                dot += __shfl_xor_sync(0xFFFFFFFFu, dot, off);
            float sc = fmaf(-2.0f, dot, g_cnorm[j]);
            if (sc < best_s || (sc == best_s && j < best_j)) {
                best_s = sc;
                best_j = j;
            }
        }
    }
    if (lane == 0) g_idx[tok] = best_j;
}

// ---------------------------------------------------------------------------
// Kernel 4: gather. One block per 32 tokens; staged codebook rows in smem.
__global__ void gather_kernel(const float* __restrict__ x,
                              const float* __restrict__ cb,
                              float* __restrict__ out) {
    __shared__ float qs[32][257];
    __shared__ float red[256];
    const int blk = blockIdx.x;
    const int tok0 = blk * 32;
    const int b = tok0 >> 10, hw0 = tok0 & 1023;
    const int tid = threadIdx.x;
    const int wid = tid >> 5, lane = tid & 31;

#pragma unroll 1
    for (int r = 0; r < 32; r++) {
        unsigned int idx = g_idx[tok0 + r];
        qs[r][tid] = cb[(size_t)idx * C_ + tid];
    }
    if (tid < 32) out[NQE + 1 + tok0 + tid] = (float)g_idx[tok0 + tid];
    __syncthreads();

    float lsum = 0.0f;
#pragma unroll
    for (int i = 0; i < 32; i++) {
        int c = wid * 32 + i;
        float q = qs[lane][c];
        size_t off = ((size_t)(b * C_ + c)) * HW_ + hw0 + lane;
        float dd = x[off] - q;
        lsum += dd * dd;
        out[off] = q;
    }
    red[tid] = lsum;
    __syncthreads();
#pragma unroll
    for (int s = 128; s; s >>= 1) {
        if (tid < s) red[tid] += red[tid + s];
        __syncthreads();
    }
    if (tid == 0) g_partial[blk] = red[0];
}

// Kernel 5: deterministic final loss reduction (512 partials)
__global__ void loss_kernel(float* __restrict__ out) {
    __shared__ float red[256];
    float s = 0.0f;
    for (int i = threadIdx.x; i < N_ / 32; i += 256) s += g_partial[i];
    red[threadIdx.x] = s;
    __syncthreads();
#pragma unroll
    for (int st = 128; st; st >>= 1) {
        if (threadIdx.x < st) red[threadIdx.x] += red[threadIdx.x + st];
        __syncthreads();
    }
    if (threadIdx.x == 0)
        out[NQE] = red[0] / (float)((size_t)N_ * C_);
}

// ---------------------------------------------------------------------------
extern "C" void kernel_launch(void* const* d_in, const int* in_sizes, int n_in,
                              void* d_out, int out_size) {
    const float* x  = (const float*)d_in[0];   // [16,256,32,32]
    const float* cb = (const float*)d_in[1];   // [8192,256]
    float* out = (float*)d_out;                // [qe | loss | indices]

    cudaFuncSetAttribute(argmin_mma_kernel,
                         cudaFuncAttributeMaxDynamicSharedMemorySize,
                         SMEM_BYTES);

    pconv_x_kernel<<<B_ * 64, 256>>>(x);
    pconv_cb_kernel<<<K_ / 8, 256>>>(cb);
    pconv_xt_kernel<<<B_ * 256, 256>>>(x);
    dim3 grid(N_ / TM, K_ / TN);
    argmin_mma_kernel<<<grid, 256, SMEM_BYTES>>>();
    rerank_kernel<<<N_ / 8, 256>>>(cb);
    gather_kernel<<<N_ / 32, 256>>>(x, cb, out);
    loss_kernel<<<1, 256>>>(out);
}